// round 2
// baseline (speedup 1.0000x reference)
#include <cuda_runtime.h>
#include <math.h>

#define V 7
#define NODE_D 48
#define OP_D 48
#define HID 96
#define GCN_D 128
#define N_LAYERS 5
#define MLP_H 200
#define NONE_OP 3

#define G 16            // graphs per CTA
#define YSTRIDE 132     // padded row stride (floats) for Ysm

// ---- shared memory layout (in floats) ----
#define OFF_Y 0
#define NY (G*V*YSTRIDE)                 // 14784
#define OFF_W (OFF_Y + NY)               // 14784
#define NW (GCN_D*GCN_D)                 // 16384
#define OFF_G (OFF_W + NW)               // 31168
#define NG (N_LAYERS*6*GCN_D)            // 3840
#define OFF_S0 (OFF_G + NG)              // 35008
#define NS0 (V*GCN_D)                    // 896
#define OFF_B (OFF_S0 + NS0)             // 35904
#define NB (N_LAYERS*GCN_D)              // 640
#define OFF_META (OFF_B + NB)            // 36544
#define SMEM_FLOATS (OFF_META + 3*G*V)   // 36880 floats = 147520 B

// Precomputed, batch-independent tables
__device__ float g_s0[V*GCN_D];              // support of layer 0 (same for all graphs)
__device__ float g_gate[N_LAYERS*6*GCN_D];   // sigmoid gates for the 6 possible op-embeddings

__global__ void precompute_kernel(
    const float* __restrict__ input_node_emb,
    const float* __restrict__ other_node_emb,
    const float* __restrict__ input_op_emb,
    const float* __restrict__ op_emb_table,
    const float* __restrict__ output_op_emb,
    const float* __restrict__ xh_w,
    const float* __restrict__ xh_b,
    const float* __restrict__ gcn0_w,
    const float* __restrict__ attn_w,
    const float* __restrict__ attn_b)
{
    __shared__ float y0[2][HID];
    int t = threadIdx.x;
    if (t < 2*HID) {
        int r = t / HID, c = t % HID;
        const float* e = (r == 0) ? input_node_emb : other_node_emb;
        float acc = xh_b[c];
        for (int d = 0; d < NODE_D; d++) acc += e[d] * xh_w[d*HID + c];
        y0[r][c] = acc;
    }
    __syncthreads();
    // s0[v][n] = y0[v] @ gcn0_w  (row 0 uses input emb, rows 1..6 identical)
    for (int idx = t; idx < V*GCN_D; idx += blockDim.x) {
        int v = idx / GCN_D, n = idx % GCN_D;
        const float* yr = y0[(v == 0) ? 0 : 1];
        float acc = 0.f;
        for (int d = 0; d < HID; d++) acc += yr[d] * gcn0_w[d*GCN_D + n];
        g_s0[idx] = acc;
    }
    // gate[i][gi][n], gi: 0=input, 1..4=op0..3, 5=output
    for (int idx = t; idx < N_LAYERS*6*GCN_D; idx += blockDim.x) {
        int i = idx / (6*GCN_D);
        int r = idx % (6*GCN_D);
        int gi = r / GCN_D, n = r % GCN_D;
        const float* e = (gi == 0) ? input_op_emb
                       : (gi <= 4 ? op_emb_table + (gi-1)*OP_D : output_op_emb);
        float acc = attn_b[i*GCN_D + n];
        for (int d = 0; d < OP_D; d++) acc += e[d] * attn_w[(i*OP_D + d)*GCN_D + n];
        g_gate[idx] = 1.f / (1.f + expf(-acc));
    }
}

__global__ __launch_bounds__(256, 1) void nb101_main(
    const float* __restrict__ adjs,
    const int*   __restrict__ op_inds,
    const float* __restrict__ gcn_w,
    const float* __restrict__ gcn_b,
    const float* __restrict__ mlp_w1,
    const float* __restrict__ mlp_b1,
    const float* __restrict__ mlp_w2,
    const float* __restrict__ mlp_b2,
    float* __restrict__ out,
    int Btot)
{
    extern __shared__ float sm[];
    float* Ysm = sm + OFF_Y;
    float* Wsm = sm + OFF_W;
    float* Gsm = sm + OFF_G;
    float* S0  = sm + OFF_S0;
    float* Bsm = sm + OFF_B;
    int*   MMask = (int*)(sm + OFF_META);
    int*   MGate = MMask + G*V;
    float* MRead = (float*)(MGate + G*V);

    const int t  = threadIdx.x;
    const int tx = t & 15;       // output-column group
    const int ty = t >> 4;       // graph within CTA
    const int gbase = blockIdx.x * G;

    // stage constant tables into smem
    for (int i = t; i < NG;  i += 256) Gsm[i] = g_gate[i];
    for (int i = t; i < NS0; i += 256) S0[i]  = g_s0[i];
    for (int i = t; i < NB;  i += 256) Bsm[i] = gcn_b[i];

    // per-graph metadata: adjacency bitmask (incl. diagonal), gate index, readout weight
    if (t < G*V) {
        int g = t / V, u = t % V;
        int batch = gbase + g;
        int m = 0, gi = 0;
        float rw = 0.f;
        if (batch < Btot) {
            const float* arow = adjs + (size_t)batch*(V*V) + u*V;
            m = 1 << u;
            #pragma unroll
            for (int v2 = 0; v2 < V; v2++) if (arow[v2] != 0.f) m |= 1 << v2;
            if (u == 0)        { gi = 0; rw = 0.f; }
            else if (u == V-1) { gi = 5; rw = 1.f/6.f; }
            else {
                int op = op_inds[(size_t)batch*(V-2) + (u-1)];
                gi = 1 + op;
                rw = (op != NONE_OP) ? (1.f/6.f) : 0.f;
            }
        }
        MMask[t] = m; MGate[t] = gi; MRead[t] = rw;
    }
    __syncthreads();

    // ----- layer 0: y1 = relu(gate0 * (mask-sum of s0 rows) + b0) -----
    for (int idx = t; idx < G*V*GCN_D; idx += 256) {
        int g = idx / (V*GCN_D);
        int r = idx - g*(V*GCN_D);
        int u = r >> 7;
        int n = r & 127;
        int m = MMask[g*V + u];
        float s = 0.f;
        #pragma unroll
        for (int v2 = 0; v2 < V; v2++) s += ((m >> v2) & 1) ? S0[v2*GCN_D + n] : 0.f;
        float y = Gsm[MGate[g*V + u]*GCN_D + n] * s + Bsm[n];
        Ysm[(g*V + u)*YSTRIDE + n] = fmaxf(y, 0.f);
    }

    // cache own-graph metadata in registers
    int myMask[V]; int myGate[V]; float myRead[V];
    #pragma unroll
    for (int u = 0; u < V; u++) {
        myMask[u] = MMask[ty*V + u];
        myGate[u] = MGate[ty*V + u];
        myRead[u] = MRead[ty*V + u];
    }

    const int n0 = tx * 8;
    float z[8];

    // ----- layers 1..4: support = Y @ W; y = gate * (A_aug @ support) + b (relu except last) -----
    for (int li = 1; li < N_LAYERS; li++) {
        __syncthreads();
        {   // load this layer's 128x128 weight into smem
            const float4* wg = (const float4*)(gcn_w + (size_t)(li-1)*GCN_D*GCN_D);
            float4* ws = (float4*)Wsm;
            for (int i = t; i < NW/4; i += 256) ws[i] = wg[i];
        }
        __syncthreads();

        float acc[V][8];
        #pragma unroll
        for (int u = 0; u < V; u++)
            #pragma unroll
            for (int j = 0; j < 8; j++) acc[u][j] = 0.f;

        const float* yrow = Ysm + ty*V*YSTRIDE;
        #pragma unroll 4
        for (int k = 0; k < GCN_D; k++) {
            float a[V];
            #pragma unroll
            for (int v2 = 0; v2 < V; v2++) a[v2] = yrow[v2*YSTRIDE + k];
            float4 b0 = *(const float4*)(Wsm + k*GCN_D + n0);
            float4 b1 = *(const float4*)(Wsm + k*GCN_D + n0 + 4);
            float bb[8] = {b0.x, b0.y, b0.z, b0.w, b1.x, b1.y, b1.z, b1.w};
            #pragma unroll
            for (int v2 = 0; v2 < V; v2++)
                #pragma unroll
                for (int j = 0; j < 8; j++)
                    acc[v2][j] = fmaf(a[v2], bb[j], acc[v2][j]);
        }

        // aggregate (registers only)
        float yn[V][8];
        const bool last = (li == N_LAYERS-1);
        #pragma unroll
        for (int u = 0; u < V; u++) {
            int m = myMask[u];
            const float* gp = Gsm + li*6*GCN_D + myGate[u]*GCN_D + n0;
            const float* bp = Bsm + li*GCN_D + n0;
            #pragma unroll
            for (int j = 0; j < 8; j++) {
                float s = 0.f;
                #pragma unroll
                for (int v2 = 0; v2 < V; v2++) s += ((m >> v2) & 1) ? acc[v2][j] : 0.f;
                float yv = gp[j]*s + bp[j];
                yn[u][j] = last ? yv : fmaxf(yv, 0.f);
            }
        }

        __syncthreads();    // all Ysm/Wsm reads done before overwrite
        if (!last) {
            float* wr = Ysm + ty*V*YSTRIDE + n0;
            #pragma unroll
            for (int u = 0; u < V; u++) {
                *(float4*)(wr + u*YSTRIDE)     = make_float4(yn[u][0], yn[u][1], yn[u][2], yn[u][3]);
                *(float4*)(wr + u*YSTRIDE + 4) = make_float4(yn[u][4], yn[u][5], yn[u][6], yn[u][7]);
            }
        } else {
            // masked-mean readout into z, stored at this graph's row 0
            #pragma unroll
            for (int j = 0; j < 8; j++) {
                float zz = 0.f;
                #pragma unroll
                for (int u = 0; u < V; u++) zz += myRead[u] * yn[u][j];
                z[j] = zz;
            }
            float* wr = Ysm + ty*V*YSTRIDE + n0;
            *(float4*)(wr)     = make_float4(z[0], z[1], z[2], z[3]);
            *(float4*)(wr + 4) = make_float4(z[4], z[5], z[6], z[7]);
        }
    }
    __syncthreads();

    // ----- MLP: score = relu(z @ w1 + b1) @ w2 + b2 -----
    const float* zrow = Ysm + ty*V*YSTRIDE;
    float accm[13];
    #pragma unroll
    for (int c = 0; c < 13; c++) accm[c] = 0.f;
    for (int k = 0; k < GCN_D; k++) {
        float zk = zrow[k];
        const float* w1p = mlp_w1 + (size_t)k*MLP_H + tx;
        #pragma unroll
        for (int c = 0; c < 13; c++) {
            int j = tx + 16*c;
            if (j < MLP_H) accm[c] = fmaf(zk, w1p[16*c], accm[c]);
        }
    }
    float part = 0.f;
    #pragma unroll
    for (int c = 0; c < 13; c++) {
        int j = tx + 16*c;
        if (j < MLP_H) part += fmaxf(accm[c] + mlp_b1[j], 0.f) * mlp_w2[j];
    }
    // reduce across the 16 threads sharing this graph (lanes form 16-wide groups)
    #pragma unroll
    for (int o = 8; o > 0; o >>= 1) part += __shfl_down_sync(0xffffffffu, part, o, 16);
    if (tx == 0 && (gbase + ty) < Btot) out[gbase + ty] = part + mlp_b2[0];
}

extern "C" void kernel_launch(void* const* d_in, const int* in_sizes, int n_in,
                              void* d_out, int out_size)
{
    const float* adjs           = (const float*)d_in[0];
    const int*   op_inds        = (const int*)  d_in[1];
    const float* input_node_emb = (const float*)d_in[2];
    const float* other_node_emb = (const float*)d_in[3];
    const float* input_op_emb   = (const float*)d_in[4];
    const float* op_emb_table   = (const float*)d_in[5];
    const float* output_op_emb  = (const float*)d_in[6];
    const float* xh_w           = (const float*)d_in[7];
    const float* xh_b           = (const float*)d_in[8];
    const float* gcn0_w         = (const float*)d_in[9];
    const float* gcn_w          = (const float*)d_in[10];
    const float* attn_w         = (const float*)d_in[11];
    const float* attn_b         = (const float*)d_in[12];
    const float* gcn_b          = (const float*)d_in[13];
    const float* mlp_w1         = (const float*)d_in[14];
    const float* mlp_b1         = (const float*)d_in[15];
    const float* mlp_w2         = (const float*)d_in[16];
    const float* mlp_b2         = (const float*)d_in[17];
    float* out = (float*)d_out;

    int Btot = in_sizes[0] / (V*V);

    precompute_kernel<<<1, 256>>>(input_node_emb, other_node_emb, input_op_emb,
                                  op_emb_table, output_op_emb, xh_w, xh_b,
                                  gcn0_w, attn_w, attn_b);

    size_t smem = SMEM_FLOATS * sizeof(float);
    cudaFuncSetAttribute(nb101_main, cudaFuncAttributeMaxDynamicSharedMemorySize, (int)smem);
    int grid = (Btot + G - 1) / G;
    nb101_main<<<grid, 256, smem>>>(adjs, op_inds, gcn_w, gcn_b,
                                    mlp_w1, mlp_b1, mlp_w2, mlp_b2, out, Btot);
}

// round 4
// speedup vs baseline: 1.1456x; 1.1456x over previous
#include <cuda_runtime.h>
#include <math.h>

#define V 7
#define NODE_D 48
#define OP_D 48
#define HID 96
#define GCN_D 128
#define N_LAYERS 5
#define MLP_H 200
#define NONE_OP 3

#define G 16            // graphs per CTA
#define NTHREADS 512    // 32 column-lanes x 16 graphs
#define YSTRIDE 132     // padded row stride (floats) for Ysm

// ---- shared memory layout (in floats) ----
#define OFF_Y 0
#define NY (G*V*YSTRIDE)                 // 14784
#define OFF_W (OFF_Y + NY)               // 14784
#define NW (GCN_D*GCN_D)                 // 16384
#define OFF_G (OFF_W + NW)               // 31168
#define NG (N_LAYERS*6*GCN_D)            // 3840
#define OFF_S0 (OFF_G + NG)              // 35008
#define NS0 (V*GCN_D)                    // 896
#define OFF_B (OFF_S0 + NS0)             // 35904
#define NB (N_LAYERS*GCN_D)              // 640
#define OFF_META (OFF_B + NB)            // 36544
#define SMEM_FLOATS (OFF_META + 3*G*V)   // 36880 floats = 147520 B

typedef unsigned long long ull;

__device__ __forceinline__ ull pack2(float x, float y) {
    ull r; asm("mov.b64 %0, {%1, %2};" : "=l"(r) : "f"(x), "f"(y)); return r;
}
__device__ __forceinline__ void unpack2(ull v, float& x, float& y) {
    asm("mov.b64 {%0, %1}, %2;" : "=f"(x), "=f"(y) : "l"(v));
}
__device__ __forceinline__ void fma2(ull& d, ull a, ull b, ull c) {
    asm("fma.rn.f32x2 %0, %1, %2, %3;" : "=l"(d) : "l"(a), "l"(b), "l"(c));
}
__device__ __forceinline__ void add2(ull& d, ull a, ull b) {
    asm("add.rn.f32x2 %0, %1, %2;" : "=l"(d) : "l"(a), "l"(b));
}

// Precomputed, batch-independent tables
__device__ float g_s0[V*GCN_D];              // support of layer 0 (same for all graphs)
__device__ float g_gate[N_LAYERS*6*GCN_D];   // sigmoid gates for the 6 possible op-embeddings

__global__ void precompute_kernel(
    const float* __restrict__ input_node_emb,
    const float* __restrict__ other_node_emb,
    const float* __restrict__ input_op_emb,
    const float* __restrict__ op_emb_table,
    const float* __restrict__ output_op_emb,
    const float* __restrict__ xh_w,
    const float* __restrict__ xh_b,
    const float* __restrict__ gcn0_w,
    const float* __restrict__ attn_w,
    const float* __restrict__ attn_b)
{
    __shared__ float y0[2][HID];
    int t = threadIdx.x;
    if (t < 2*HID) {
        int r = t / HID, c = t % HID;
        const float* e = (r == 0) ? input_node_emb : other_node_emb;
        float acc = xh_b[c];
        for (int d = 0; d < NODE_D; d++) acc += e[d] * xh_w[d*HID + c];
        y0[r][c] = acc;
    }
    __syncthreads();
    for (int idx = t; idx < V*GCN_D; idx += blockDim.x) {
        int v = idx / GCN_D, n = idx % GCN_D;
        const float* yr = y0[(v == 0) ? 0 : 1];
        float acc = 0.f;
        for (int d = 0; d < HID; d++) acc += yr[d] * gcn0_w[d*GCN_D + n];
        g_s0[idx] = acc;
    }
    for (int idx = t; idx < N_LAYERS*6*GCN_D; idx += blockDim.x) {
        int i = idx / (6*GCN_D);
        int r = idx % (6*GCN_D);
        int gi = r / GCN_D, n = r % GCN_D;
        const float* e = (gi == 0) ? input_op_emb
                       : (gi <= 4 ? op_emb_table + (gi-1)*OP_D : output_op_emb);
        float acc = attn_b[i*GCN_D + n];
        for (int d = 0; d < OP_D; d++) acc += e[d] * attn_w[(i*OP_D + d)*GCN_D + n];
        g_gate[idx] = 1.f / (1.f + expf(-acc));
    }
}

__global__ __launch_bounds__(NTHREADS, 1) void nb101_main(
    const float* __restrict__ adjs,
    const int*   __restrict__ op_inds,
    const float* __restrict__ gcn_w,
    const float* __restrict__ gcn_b,
    const float* __restrict__ mlp_w1,
    const float* __restrict__ mlp_b1,
    const float* __restrict__ mlp_w2,
    const float* __restrict__ mlp_b2,
    float* __restrict__ out,
    int Btot)
{
    extern __shared__ float sm[];
    float* Ysm = sm + OFF_Y;
    float* Wsm = sm + OFF_W;
    float* Gsm = sm + OFF_G;
    float* S0  = sm + OFF_S0;
    float* Bsm = sm + OFF_B;
    int*   MMask = (int*)(sm + OFF_META);
    int*   MGate = MMask + G*V;
    float* MRead = (float*)(MGate + G*V);

    const int t  = threadIdx.x;
    const int tx = t & 31;       // output-column lane (4 cols each)
    const int ty = t >> 5;       // graph within CTA (one warp per graph)
    const int gbase = blockIdx.x * G;

    // stage constant tables into smem
    for (int i = t; i < NG;  i += NTHREADS) Gsm[i] = g_gate[i];
    for (int i = t; i < NS0; i += NTHREADS) S0[i]  = g_s0[i];
    for (int i = t; i < NB;  i += NTHREADS) Bsm[i] = gcn_b[i];

    // per-graph metadata: adjacency bitmask (incl. diagonal), gate index, readout weight
    if (t < G*V) {
        int g = t / V, u = t % V;
        int batch = gbase + g;
        int m = 0, gi = 0;
        float rw = 0.f;
        if (batch < Btot) {
            const float* arow = adjs + (size_t)batch*(V*V) + u*V;
            m = 1 << u;
            #pragma unroll
            for (int v2 = 0; v2 < V; v2++) if (arow[v2] != 0.f) m |= 1 << v2;
            if (u == 0)        { gi = 0; rw = 0.f; }
            else if (u == V-1) { gi = 5; rw = 1.f/6.f; }
            else {
                int op = op_inds[(size_t)batch*(V-2) + (u-1)];
                gi = 1 + op;
                rw = (op != NONE_OP) ? (1.f/6.f) : 0.f;
            }
        }
        MMask[t] = m; MGate[t] = gi; MRead[t] = rw;
    }
    __syncthreads();

    // ----- layer 0: y1 = relu(gate0 * (mask-sum of s0 rows) + b0) -----
    for (int idx = t; idx < G*V*GCN_D; idx += NTHREADS) {
        int g = idx / (V*GCN_D);
        int r = idx - g*(V*GCN_D);
        int u = r >> 7;
        int n = r & 127;
        int m = MMask[g*V + u];
        float s = 0.f;
        #pragma unroll
        for (int v2 = 0; v2 < V; v2++) s += ((m >> v2) & 1) ? S0[v2*GCN_D + n] : 0.f;
        float y = Gsm[MGate[g*V + u]*GCN_D + n] * s + Bsm[n];
        Ysm[(g*V + u)*YSTRIDE + n] = fmaxf(y, 0.f);
    }

    // cache own-graph metadata in registers
    int myMask[V]; int myGate[V]; float myRead[V];
    #pragma unroll
    for (int u = 0; u < V; u++) {
        myMask[u] = MMask[ty*V + u];
        myGate[u] = MGate[ty*V + u];
        myRead[u] = MRead[ty*V + u];
    }

    const int n0 = tx * 4;
    float z[4];

    // ----- layers 1..4: support = Y @ W; y = gate * (A_aug @ support) + b -----
    for (int li = 1; li < N_LAYERS; li++) {
        __syncthreads();
        {   // load this layer's 128x128 weight into smem
            const float4* wg = (const float4*)(gcn_w + (size_t)(li-1)*GCN_D*GCN_D);
            float4* ws = (float4*)Wsm;
            for (int i = t; i < NW/4; i += NTHREADS) ws[i] = wg[i];
        }
        __syncthreads();

        ull acc[V][2];
        #pragma unroll
        for (int u = 0; u < V; u++) { acc[u][0] = 0ull; acc[u][1] = 0ull; }

        const float* yrow = Ysm + ty*(V*YSTRIDE);
        #pragma unroll 4
        for (int k = 0; k < GCN_D; k += 2) {
            ulonglong2 b0 = *(const ulonglong2*)(Wsm + k*GCN_D + n0);
            ulonglong2 b1 = *(const ulonglong2*)(Wsm + (k+1)*GCN_D + n0);
            #pragma unroll
            for (int v2 = 0; v2 < V; v2++) {
                float2 a = *(const float2*)(yrow + v2*YSTRIDE + k);
                ull ax = pack2(a.x, a.x);
                fma2(acc[v2][0], ax, b0.x, acc[v2][0]);
                fma2(acc[v2][1], ax, b0.y, acc[v2][1]);
                ull ay = pack2(a.y, a.y);
                fma2(acc[v2][0], ay, b1.x, acc[v2][0]);
                fma2(acc[v2][1], ay, b1.y, acc[v2][1]);
            }
        }

        // aggregate + gate + bias (packed), registers only
        float yn[V][4];
        const bool last = (li == N_LAYERS-1);
        #pragma unroll
        for (int u = 0; u < V; u++) {
            int m = myMask[u];
            const ull* gp = (const ull*)(Gsm + li*6*GCN_D + myGate[u]*GCN_D + n0);
            const ull* bp = (const ull*)(Bsm + li*GCN_D + n0);
            ull s0p = 0ull, s1p = 0ull;
            #pragma unroll
            for (int v2 = 0; v2 < V; v2++) {
                if ((m >> v2) & 1) {
                    add2(s0p, s0p, acc[v2][0]);
                    add2(s1p, s1p, acc[v2][1]);
                }
            }
            ull y0p, y1p;
            fma2(y0p, gp[0], s0p, bp[0]);
            fma2(y1p, gp[1], s1p, bp[1]);
            unpack2(y0p, yn[u][0], yn[u][1]);
            unpack2(y1p, yn[u][2], yn[u][3]);
            if (!last) {
                #pragma unroll
                for (int j = 0; j < 4; j++) yn[u][j] = fmaxf(yn[u][j], 0.f);
            }
        }

        __syncthreads();    // all Ysm/Wsm reads done before overwrite
        if (!last) {
            float* wr = Ysm + ty*(V*YSTRIDE) + n0;
            #pragma unroll
            for (int u = 0; u < V; u++)
                *(float4*)(wr + u*YSTRIDE) = make_float4(yn[u][0], yn[u][1], yn[u][2], yn[u][3]);
        } else {
            // masked-mean readout into z, stored at this graph's row 0
            #pragma unroll
            for (int j = 0; j < 4; j++) {
                float zz = 0.f;
                #pragma unroll
                for (int u = 0; u < V; u++) zz += myRead[u] * yn[u][j];
                z[j] = zz;
            }
            *(float4*)(Ysm + ty*(V*YSTRIDE) + n0) = make_float4(z[0], z[1], z[2], z[3]);
        }
    }
    __syncthreads();

    // ----- MLP: score = relu(z @ w1 + b1) @ w2 + b2  (one warp per graph) -----
    const float* zrow = Ysm + ty*(V*YSTRIDE);
    float accm[7];
    #pragma unroll
    for (int c = 0; c < 7; c++) accm[c] = 0.f;
    for (int k = 0; k < GCN_D; k++) {
        float zk = zrow[k];
        const float* w1p = mlp_w1 + (size_t)k*MLP_H + tx;
        #pragma unroll
        for (int c = 0; c < 7; c++) {
            int j = tx + 32*c;
            if (j < MLP_H) accm[c] = fmaf(zk, w1p[32*c], accm[c]);
        }
    }
    float part = 0.f;
    #pragma unroll
    for (int c = 0; c < 7; c++) {
        int j = tx + 32*c;
        if (j < MLP_H) part += fmaxf(accm[c] + mlp_b1[j], 0.f) * mlp_w2[j];
    }
    #pragma unroll
    for (int o = 16; o > 0; o >>= 1) part += __shfl_down_sync(0xffffffffu, part, o);
    if (tx == 0 && (gbase + ty) < Btot) out[gbase + ty] = part + mlp_b2[0];
}

extern "C" void kernel_launch(void* const* d_in, const int* in_sizes, int n_in,
                              void* d_out, int out_size)
{
    const float* adjs           = (const float*)d_in[0];
    const int*   op_inds        = (const int*)  d_in[1];
    const float* input_node_emb = (const float*)d_in[2];
    const float* other_node_emb = (const float*)d_in[3];
    const float* input_op_emb   = (const float*)d_in[4];
    const float* op_emb_table   = (const float*)d_in[5];
    const float* output_op_emb  = (const float*)d_in[6];
    const float* xh_w           = (const float*)d_in[7];
    const float* xh_b           = (const float*)d_in[8];
    const float* gcn0_w         = (const float*)d_in[9];
    const float* gcn_w          = (const float*)d_in[10];
    const float* attn_w         = (const float*)d_in[11];
    const float* attn_b         = (const float*)d_in[12];
    const float* gcn_b          = (const float*)d_in[13];
    const float* mlp_w1         = (const float*)d_in[14];
    const float* mlp_b1         = (const float*)d_in[15];
    const float* mlp_w2         = (const float*)d_in[16];
    const float* mlp_b2         = (const float*)d_in[17];
    float* out = (float*)d_out;

    int Btot = in_sizes[0] / (V*V);

    precompute_kernel<<<1, 256>>>(input_node_emb, other_node_emb, input_op_emb,
                                  op_emb_table, output_op_emb, xh_w, xh_b,
                                  gcn0_w, attn_w, attn_b);

    size_t smem = SMEM_FLOATS * sizeof(float);
    cudaFuncSetAttribute(nb101_main, cudaFuncAttributeMaxDynamicSharedMemorySize, (int)smem);
    int grid = (Btot + G - 1) / G;
    nb101_main<<<grid, NTHREADS, smem>>>(adjs, op_inds, gcn_w, gcn_b,
                                         mlp_w1, mlp_b1, mlp_w2, mlp_b2, out, Btot);
}

// round 6
// speedup vs baseline: 1.3741x; 1.1996x over previous
#include <cuda_runtime.h>
#include <math.h>
#include <stdint.h>

#define V 7
#define NODE_D 48
#define OP_D 48
#define HID 96
#define GCN_D 128
#define N_LAYERS 5
#define MLP_H 200
#define NONE_OP 3

#define G 32             // graphs per CTA
#define NTHREADS 512     // 16 warps; each warp handles 2 graphs (16 lanes each)

// ---- shared memory layout (float offsets) ----
#define OFF_Y 0
#define NY (G*V*GCN_D)                  // 28672  (graph-major [g][u][n], stride 128)
#define OFF_W (OFF_Y + NY)              // 28672
#define NW (GCN_D*GCN_D)                // 16384
#define OFF_G (OFF_W + NW)              // 45056
#define NG (N_LAYERS*6*GCN_D)           // 3840
#define OFF_S0 (OFF_G + NG)             // 48896
#define NS0 (V*GCN_D)                   // 896
#define OFF_B (OFF_S0 + NS0)            // 49792
#define NB (N_LAYERS*GCN_D)             // 640
#define OFF_META (OFF_B + NB)           // 50432
#define SMEM_FLOATS (OFF_META + 3*G*V)  // 51104 floats = 204416 B

typedef unsigned long long ull;

__device__ __forceinline__ ull pack2(float x, float y) {
    ull r; asm("mov.b64 %0, {%1, %2};" : "=l"(r) : "f"(x), "f"(y)); return r;
}
__device__ __forceinline__ void unpack2(ull v, float& x, float& y) {
    asm("mov.b64 {%0, %1}, %2;" : "=f"(x), "=f"(y) : "l"(v));
}
__device__ __forceinline__ void fma2(ull& d, ull a, ull b, ull c) {
    asm("fma.rn.f32x2 %0, %1, %2, %3;" : "=l"(d) : "l"(a), "l"(b), "l"(c));
}
__device__ __forceinline__ void add2(ull& d, ull a, ull b) {
    asm("add.rn.f32x2 %0, %1, %2;" : "=l"(d) : "l"(a), "l"(b));
}

// Precomputed, batch-independent tables
__device__ float g_s0[V*GCN_D];              // layer-0 support (identical for all graphs)
__device__ float g_gate[N_LAYERS*6*GCN_D];   // sigmoid gates for the 6 possible op-embeddings

__global__ void precompute_kernel(
    const float* __restrict__ input_node_emb,
    const float* __restrict__ other_node_emb,
    const float* __restrict__ input_op_emb,
    const float* __restrict__ op_emb_table,
    const float* __restrict__ output_op_emb,
    const float* __restrict__ xh_w,
    const float* __restrict__ xh_b,
    const float* __restrict__ gcn0_w,
    const float* __restrict__ attn_w,
    const float* __restrict__ attn_b)
{
    __shared__ float y0[2][HID];
    int t = threadIdx.x;
    if (t < 2*HID) {
        int r = t / HID, c = t % HID;
        const float* e = (r == 0) ? input_node_emb : other_node_emb;
        float acc = xh_b[c];
        for (int d = 0; d < NODE_D; d++) acc += e[d] * xh_w[d*HID + c];
        y0[r][c] = acc;
    }
    __syncthreads();
    for (int idx = t; idx < V*GCN_D; idx += blockDim.x) {
        int v = idx / GCN_D, n = idx % GCN_D;
        const float* yr = y0[(v == 0) ? 0 : 1];
        float acc = 0.f;
        for (int d = 0; d < HID; d++) acc += yr[d] * gcn0_w[d*GCN_D + n];
        g_s0[idx] = acc;
    }
    for (int idx = t; idx < N_LAYERS*6*GCN_D; idx += blockDim.x) {
        int i = idx / (6*GCN_D);
        int r = idx % (6*GCN_D);
        int gi = r / GCN_D, n = r % GCN_D;
        const float* e = (gi == 0) ? input_op_emb
                       : (gi <= 4 ? op_emb_table + (gi-1)*OP_D : output_op_emb);
        float acc = attn_b[i*GCN_D + n];
        for (int d = 0; d < OP_D; d++) acc += e[d] * attn_w[(i*OP_D + d)*GCN_D + n];
        g_gate[idx] = 1.f / (1.f + expf(-acc));
    }
}

__global__ __launch_bounds__(NTHREADS, 1) void nb101_main(
    const float* __restrict__ adjs,
    const int*   __restrict__ op_inds,
    const float* __restrict__ gcn_w,
    const float* __restrict__ gcn_b,
    const float* __restrict__ mlp_w1,
    const float* __restrict__ mlp_b1,
    const float* __restrict__ mlp_w2,
    const float* __restrict__ mlp_b2,
    float* __restrict__ out,
    int Btot)
{
    extern __shared__ float sm[];
    float* Ysm = sm + OFF_Y;
    float* Wsm = sm + OFF_W;
    float* Gsm = sm + OFF_G;
    float* S0  = sm + OFF_S0;
    float* Bsm = sm + OFF_B;
    int*   MMask = (int*)(sm + OFF_META);
    int*   MGate = MMask + G*V;
    float* MRead = (float*)(MGate + G*V);

    const int t  = threadIdx.x;
    const int tx = t & 31;
    const int ty = t >> 5;            // warp id
    const int half = tx >> 4;         // which graph within the warp
    const int lx = tx & 15;           // lane within half-warp
    const int gl = ty*2 + half;       // this lane's graph (0..31)
    const int n0 = lx * 8;            // 8 output columns per lane
    const int gbase = blockIdx.x * G;

    // stage constant tables
    for (int i = t; i < NG;  i += NTHREADS) Gsm[i] = g_gate[i];
    for (int i = t; i < NS0; i += NTHREADS) S0[i]  = g_s0[i];
    for (int i = t; i < NB;  i += NTHREADS) Bsm[i] = gcn_b[i];

    // per-graph metadata: adjacency bitmask (incl. diag), gate index, readout weight
    for (int mi = t; mi < G*V; mi += NTHREADS) {
        int g = mi / V, u = mi % V;
        int batch = gbase + g;
        int m = 0, gi = 0;
        float rw = 0.f;
        if (batch < Btot) {
            const float* arow = adjs + (size_t)batch*(V*V) + u*V;
            m = 1 << u;
            #pragma unroll
            for (int v2 = 0; v2 < V; v2++) if (arow[v2] != 0.f) m |= 1 << v2;
            if (u == 0)        { gi = 0; rw = 0.f; }
            else if (u == V-1) { gi = 5; rw = 1.f/6.f; }
            else {
                int op = op_inds[(size_t)batch*(V-2) + (u-1)];
                gi = 1 + op;
                rw = (op != NONE_OP) ? (1.f/6.f) : 0.f;
            }
        }
        MMask[mi] = m; MGate[mi] = gi; MRead[mi] = rw;
    }
    __syncthreads();

    // ----- layer 0: y1 = relu(gate0 * (mask-sum of s0 rows) + b0) -----
    for (int idx = t; idx < G*V*GCN_D; idx += NTHREADS) {
        int g = idx / (V*GCN_D);
        int r = idx - g*(V*GCN_D);
        int u = r >> 7;
        int n = r & 127;
        int m = MMask[g*V + u];
        float s = 0.f;
        #pragma unroll
        for (int v2 = 0; v2 < V; v2++) s += ((m >> v2) & 1) ? S0[v2*GCN_D + n] : 0.f;
        float y = Gsm[MGate[g*V + u]*GCN_D + n] * s + Bsm[n];
        Ysm[idx] = fmaxf(y, 0.f);   // [g][u][n] layout matches idx directly
    }

    float z[8];

    // ----- layers 1..4: support = Y @ W; y = gate * (A_aug @ support) + b -----
    for (int li = 1; li < N_LAYERS; li++) {
        __syncthreads();   // previous layer's Wsm/Ysm reads complete
        {   // stage this layer's 128x128 weight
            const float4* wg = (const float4*)(gcn_w + (size_t)(li-1)*GCN_D*GCN_D);
            float4* ws = (float4*)Wsm;
            for (int i = t; i < NW/4; i += NTHREADS) ws[i] = wg[i];
        }
        __syncthreads();

        // GEMM: acc[u][c] covers cols n0+2c, n0+2c+1 of this lane's graph
        ull acc[V][4];
        #pragma unroll
        for (int u = 0; u < V; u++)
            #pragma unroll
            for (int c = 0; c < 4; c++) acc[u][c] = 0ull;

        const float* yrow = Ysm + gl*(V*GCN_D);
        #pragma unroll 2
        for (int k = 0; k < GCN_D; k += 4) {
            float4 a[V];
            #pragma unroll
            for (int u = 0; u < V; u++) a[u] = *(const float4*)(yrow + u*GCN_D + k);
            #pragma unroll
            for (int kk = 0; kk < 4; kk++) {
                ulonglong2 b0 = *(const ulonglong2*)(Wsm + (k+kk)*GCN_D + n0);
                ulonglong2 b1 = *(const ulonglong2*)(Wsm + (k+kk)*GCN_D + n0 + 4);
                #pragma unroll
                for (int u = 0; u < V; u++) {
                    float av = (kk == 0) ? a[u].x : (kk == 1) ? a[u].y : (kk == 2) ? a[u].z : a[u].w;
                    ull ap = pack2(av, av);
                    fma2(acc[u][0], ap, b0.x, acc[u][0]);
                    fma2(acc[u][1], ap, b0.y, acc[u][1]);
                    fma2(acc[u][2], ap, b1.x, acc[u][2]);
                    fma2(acc[u][3], ap, b1.y, acc[u][3]);
                }
            }
        }

        // aggregation + gate + bias (+relu), registers only
        const bool last = (li == N_LAYERS - 1);
        float yn[V][8];
        #pragma unroll
        for (int u = 0; u < V; u++) {
            int m = MMask[gl*V + u];
            const ull* gp = (const ull*)(Gsm + li*6*GCN_D + MGate[gl*V + u]*GCN_D + n0);
            const ull* bp = (const ull*)(Bsm + li*GCN_D + n0);
            #pragma unroll
            for (int c = 0; c < 4; c++) {
                ull s = 0ull;
                #pragma unroll
                for (int v2 = 0; v2 < V; v2++)
                    if ((m >> v2) & 1) add2(s, s, acc[v2][c]);
                ull yp;
                fma2(yp, gp[c], s, bp[c]);
                unpack2(yp, yn[u][2*c], yn[u][2*c+1]);
            }
            if (!last) {
                #pragma unroll
                for (int j = 0; j < 8; j++) yn[u][j] = fmaxf(yn[u][j], 0.f);
            }
        }

        // write back (own graph, own columns — no cross-warp hazard, no barrier)
        if (!last) {
            float* wr = Ysm + gl*(V*GCN_D) + n0;
            #pragma unroll
            for (int u = 0; u < V; u++) {
                *(float4*)(wr + u*GCN_D)     = make_float4(yn[u][0], yn[u][1], yn[u][2], yn[u][3]);
                *(float4*)(wr + u*GCN_D + 4) = make_float4(yn[u][4], yn[u][5], yn[u][6], yn[u][7]);
            }
        } else {
            // masked-mean readout -> z, stored at this graph's row 0
            #pragma unroll
            for (int j = 0; j < 8; j++) {
                float zz = 0.f;
                #pragma unroll
                for (int u = 0; u < V; u++) zz += MRead[gl*V + u] * yn[u][j];
                z[j] = zz;
            }
            float* wr = Ysm + gl*(V*GCN_D) + n0;
            *(float4*)(wr)     = make_float4(z[0], z[1], z[2], z[3]);
            *(float4*)(wr + 4) = make_float4(z[4], z[5], z[6], z[7]);
        }
    }
    __syncthreads();

    // ----- MLP: warp ty handles graphs 2ty, 2ty+1; shared w1 loads -----
    {
        const float* z0 = Ysm + (ty*2    )*(V*GCN_D);
        const float* z1 = Ysm + (ty*2 + 1)*(V*GCN_D);
        float acc0[7], acc1[7];
        #pragma unroll
        for (int c = 0; c < 7; c++) { acc0[c] = 0.f; acc1[c] = 0.f; }
        for (int k = 0; k < GCN_D; k++) {
            float zk0 = z0[k], zk1 = z1[k];
            const float* w1p = mlp_w1 + (size_t)k*MLP_H + tx;
            #pragma unroll
            for (int c = 0; c < 7; c++) {
                int j = tx + 32*c;
                if (j < MLP_H) {
                    float w = __ldg(w1p + 32*c);
                    acc0[c] = fmaf(zk0, w, acc0[c]);
                    acc1[c] = fmaf(zk1, w, acc1[c]);
                }
            }
        }
        float p0 = 0.f, p1 = 0.f;
        #pragma unroll
        for (int c = 0; c < 7; c++) {
            int j = tx + 32*c;
            if (j < MLP_H) {
                float b = mlp_b1[j], w2 = mlp_w2[j];
                p0 += fmaxf(acc0[c] + b, 0.f) * w2;
                p1 += fmaxf(acc1[c] + b, 0.f) * w2;
            }
        }
        #pragma unroll
        for (int o = 16; o > 0; o >>= 1) {
            p0 += __shfl_down_sync(0xffffffffu, p0, o);
            p1 += __shfl_down_sync(0xffffffffu, p1, o);
        }
        if (tx == 0) {
            float b2 = mlp_b2[0];
            int g0 = gbase + ty*2;
            if (g0 < Btot)     out[g0]     = p0 + b2;
            if (g0 + 1 < Btot) out[g0 + 1] = p1 + b2;
        }
    }
}

extern "C" void kernel_launch(void* const* d_in, const int* in_sizes, int n_in,
                              void* d_out, int out_size)
{
    const float* adjs           = (const float*)d_in[0];
    const int*   op_inds        = (const int*)  d_in[1];
    const float* input_node_emb = (const float*)d_in[2];
    const float* other_node_emb = (const float*)d_in[3];
    const float* input_op_emb   = (const float*)d_in[4];
    const float* op_emb_table   = (const float*)d_in[5];
    const float* output_op_emb  = (const float*)d_in[6];
    const float* xh_w           = (const float*)d_in[7];
    const float* xh_b           = (const float*)d_in[8];
    const float* gcn0_w         = (const float*)d_in[9];
    const float* gcn_w          = (const float*)d_in[10];
    const float* attn_w         = (const float*)d_in[11];
    const float* attn_b         = (const float*)d_in[12];
    const float* gcn_b          = (const float*)d_in[13];
    const float* mlp_w1         = (const float*)d_in[14];
    const float* mlp_b1         = (const float*)d_in[15];
    const float* mlp_w2         = (const float*)d_in[16];
    const float* mlp_b2         = (const float*)d_in[17];
    float* out = (float*)d_out;

    int Btot = in_sizes[0] / (V*V);

    precompute_kernel<<<1, 256>>>(input_node_emb, other_node_emb, input_op_emb,
                                  op_emb_table, output_op_emb, xh_w, xh_b,
                                  gcn0_w, attn_w, attn_b);

    size_t smem = SMEM_FLOATS * sizeof(float);
    cudaFuncSetAttribute(nb101_main, cudaFuncAttributeMaxDynamicSharedMemorySize, (int)smem);
    int grid = (Btot + G - 1) / G;
    nb101_main<<<grid, NTHREADS, smem>>>(adjs, op_inds, gcn_w, gcn_b,
                                         mlp_w1, mlp_b1, mlp_w2, mlp_b2, out, Btot);
}